// round 15
// baseline (speedup 1.0000x reference)
#include <cuda_runtime.h>
#include <cuda_fp16.h>
#include <math.h>
#include <cstdint>

#define N_NODES 20000
#define N_EDGES 600000
#define HDIM 128
#define NHEADS 4
#define EB 4688   // ceil(600000/128)

// ---------------- scratch -----------------------------------------------------
__device__ float g_P[N_NODES * HDIM];
__device__ float g_num[N_NODES * HDIM];
__device__ float g_den[N_NODES * NHEADS];
__device__ float g_ew[(size_t)EB * 128 * NHEADS];   // padded per-edge exp weights

__device__ __align__(16) __half g_wv1f[32768];
__device__ __align__(16) __half g_wv2f[16384];
__device__ __align__(16) __half g_wv3f[16384];
__device__ __align__(16) __half g_wb1f[32768];
__device__ __align__(16) __half g_wb1pf[16384];   // Wb1[:, :128] (node half) for k_pre2
__device__ __align__(16) __half g_wb2f[16384];
__device__ __align__(16) __half g_wb3f[2048];

// ---------------- helpers -----------------------------------------------------
__device__ __forceinline__ float gelu_f(float x) {
    return 0.5f * x * (1.0f + erff(x * 0.70710678118654752440f));
}
__device__ __forceinline__ uint32_t smem_to_u32(const void* p) {
    uint32_t a;
    asm("{ .reg .u64 t; cvta.to.shared.u64 t, %1; cvt.u32.u64 %0, t; }" : "=r"(a) : "l"(p));
    return a;
}
__device__ __forceinline__ unsigned sw128(unsigned byte) {
    return byte ^ ((byte >> 3) & 0x70);
}
__device__ __forceinline__ unsigned pack_h2(float a, float b) {
    __half2 h = __floats2half2_rn(a, b);
    return *reinterpret_cast<unsigned*>(&h);
}
// vectorized global reductions (base PTX, sm_90+)
__device__ __forceinline__ void red2(float* addr, float a, float b) {
    asm volatile("red.global.add.v2.f32 [%0], {%1, %2};"
                 :: "l"(addr), "f"(a), "f"(b) : "memory");
}
__device__ __forceinline__ void red4(float* addr, float a, float b, float c, float d) {
    asm volatile("red.global.add.v4.f32 [%0], {%1, %2, %3, %4};"
                 :: "l"(addr), "f"(a), "f"(b), "f"(c), "f"(d) : "memory");
}

// ---------------- cp.async ------------------------------------------------------
__device__ __forceinline__ void cp16(uint32_t dst, const void* src) {
    asm volatile("cp.async.cg.shared.global [%0], [%1], 16;" :: "r"(dst), "l"(src));
}
#define CP_COMMIT() asm volatile("cp.async.commit_group;" ::: "memory")
#define CP_WAIT0()  asm volatile("cp.async.wait_group 0;" ::: "memory")
#define CP_WAIT1()  asm volatile("cp.async.wait_group 1;" ::: "memory")

__device__ __forceinline__ void cpa16k(uint32_t dst, const char* src, int tid) {
#pragma unroll
    for (int j = 0; j < 4; ++j)
        cp16(dst + tid * 16 + j * 4096, src + tid * 16 + j * 4096);
}
// raw fp32 hE chunk (128 rows x 64 floats = 32KB), coalesced; OOB rows clamped
__device__ __forceinline__ void cpa32k(uint32_t dst, const float* __restrict__ hE,
                                       size_t e0, int c, int tid) {
#pragma unroll
    for (int j = 0; j < 8; ++j) {
        int idx = tid + j * 256;            // 0..2047
        int row = idx >> 4, seg = idx & 15;
        size_t e = e0 + (size_t)row;
        if (e >= N_EDGES) e = N_EDGES - 1;
        cp16(dst + row * 256 + seg * 16,
             (const char*)hE + e * 1024 + (size_t)c * 256 + seg * 16);
    }
}
// fp32 staging (32KB) -> swizzled fp16 tile (16KB). Disjoint regions, no hazards.
__device__ __forceinline__ void conv_tile(char* sm, int S_off, int T_off, int tid) {
#pragma unroll
    for (int j = 0; j < 4; ++j) {
        int u = tid + j * 256;              // 0..1023
        int row = u >> 3, oq = u & 7;
        const float4* src = (const float4*)(sm + S_off + row * 256 + oq * 32);
        float4 a = src[0], b = src[1];
        *(uint4*)(sm + T_off + sw128((unsigned)(row * 128 + oq * 16))) =
            make_uint4(pack_h2(a.x, a.y), pack_h2(a.z, a.w),
                       pack_h2(b.x, b.y), pack_h2(b.z, b.w));
    }
}

// ---------------- mma.sync primitives ------------------------------------------
__device__ __forceinline__ void ldsm4(unsigned r[4], uint32_t addr) {
    asm volatile("ldmatrix.sync.aligned.m8n8.x4.shared.b16 {%0,%1,%2,%3}, [%4];"
        : "=r"(r[0]), "=r"(r[1]), "=r"(r[2]), "=r"(r[3]) : "r"(addr));
}
__device__ __forceinline__ void mma_f16(float c[4], const unsigned a[4], const unsigned b[2]) {
    asm volatile("mma.sync.aligned.m16n8k16.row.col.f32.f16.f16.f32 "
        "{%0,%1,%2,%3}, {%4,%5,%6,%7}, {%8,%9}, {%0,%1,%2,%3};"
        : "+f"(c[0]), "+f"(c[1]), "+f"(c[2]), "+f"(c[3])
        : "r"(a[0]), "r"(a[1]), "r"(a[2]), "r"(a[3]), "r"(b[0]), "r"(b[1]));
}

// smem byte offsets (total 102400 -> 2 CTAs/SM)
#define OFF_CE   0
#define OFF_SEW  512
#define OFF_B0   4096
#define OFF_B1   20480
#define OFF_S    36864      /* fp32 staging, 32KB */
#define OFF_T    69632      /* A fp16 tiles during L1; t1/t2 after (2 x 16KB) */
#define SMEM_E   102400
#define SMEM_P   65536

// one K=64 chunk, single fp16 pass; tiles 128x64 fp16 SW128 (128B pitch)
__device__ __forceinline__ void chunk_mma(float acc[4][4][4],
                                          uint32_t A, uint32_t B,
                                          int wm, int wn, int lid) {
    int g = lid >> 3, r = lid & 7;
    int am = (g & 1) * 8 + r, ak = (g >> 1) * 8;
    int bn = (g >> 1) * 8 + r, bk = (g & 1) * 8;
#pragma unroll
    for (int ks = 0; ks < 4; ++ks) {
        int kb = ks * 16;
        unsigned Af[4][4], Bf[4][2];
#pragma unroll
        for (int ms = 0; ms < 4; ++ms) {
            unsigned byte = (unsigned)((wm * 64 + ms * 16 + am) * 128 + (kb + ak) * 2);
            ldsm4(Af[ms], A + sw128(byte));
        }
#pragma unroll
        for (int np = 0; np < 2; ++np) {
            unsigned byte = (unsigned)((wn * 32 + np * 16 + bn) * 128 + (kb + bk) * 2);
            unsigned t[4];
            ldsm4(t, B + sw128(byte));
            Bf[np*2][0] = t[0]; Bf[np*2][1] = t[1];
            Bf[np*2+1][0] = t[2]; Bf[np*2+1][1] = t[3];
        }
#pragma unroll
        for (int ms = 0; ms < 4; ++ms)
#pragma unroll
            for (int ns = 0; ns < 4; ++ns)
                mma_f16(acc[ms][ns], Af[ms], Bf[ns]);
    }
}

// logits variant: n0-7 only, B tile 16-row padded (2KB per chunk)
__device__ __forceinline__ void chunk_mma_log(float accl[4][4],
                                              uint32_t A, uint32_t B,
                                              int wm, int lid) {
    int g = lid >> 3, r = lid & 7;
    int am = (g & 1) * 8 + r, ak = (g >> 1) * 8;
    int bn = (g >> 1) * 8 + r, bk = (g & 1) * 8;
#pragma unroll
    for (int ks = 0; ks < 4; ++ks) {
        int kb = ks * 16;
        unsigned Af[4][4], Bf[2];
#pragma unroll
        for (int ms = 0; ms < 4; ++ms) {
            unsigned byte = (unsigned)((wm * 64 + ms * 16 + am) * 128 + (kb + ak) * 2);
            ldsm4(Af[ms], A + sw128(byte));
        }
        unsigned byte = (unsigned)(bn * 128 + (kb + bk) * 2);
        unsigned t[4];
        ldsm4(t, B + sw128(byte));
        Bf[0] = t[0]; Bf[1] = t[1];
#pragma unroll
        for (int ms = 0; ms < 4; ++ms)
            mma_f16(accl[ms], Af[ms], Bf);
    }
}

// acc + add -> gelu -> fp16 -> T tiles (chunk ch @ +ch*16K)
__device__ __forceinline__ void epi_store(float acc[4][4][4], char* T,
                                          const float* __restrict__ addv,
                                          const int* __restrict__ ce, bool perrow,
                                          int wm, int wn, int lid) {
#pragma unroll
    for (int ms = 0; ms < 4; ++ms) {
        int r0 = wm * 64 + ms * 16 + (lid >> 2), r1 = r0 + 8;
#pragma unroll
        for (int ns = 0; ns < 4; ++ns) {
            int n = wn * 32 + ns * 8 + (lid & 3) * 2;
            const float* a0 = perrow ? (addv + (size_t)ce[r0] * 128 + n) : (addv + n);
            const float* a1 = perrow ? (addv + (size_t)ce[r1] * 128 + n) : (addv + n);
            float o0 = gelu_f(acc[ms][ns][0] + a0[0]);
            float o1 = gelu_f(acc[ms][ns][1] + a0[1]);
            float o2 = gelu_f(acc[ms][ns][2] + a1[0]);
            float o3 = gelu_f(acc[ms][ns][3] + a1[1]);
            int ch = n >> 6, kk = n & 63;
            char* th = T + ch * 16384;
            *(unsigned*)(th + sw128((unsigned)(r0 * 128 + kk * 2))) = pack_h2(o0, o1);
            *(unsigned*)(th + sw128((unsigned)(r1 * 128 + kk * 2))) = pack_h2(o2, o3);
        }
    }
}

#define ZERO_ACC(acc) do {                                                    \
    _Pragma("unroll") for (int _i = 0; _i < 4; ++_i)                          \
    _Pragma("unroll") for (int _j = 0; _j < 4; ++_j)                          \
    _Pragma("unroll") for (int _k = 0; _k < 4; ++_k) (acc)[_i][_j][_k] = 0.f; \
} while (0)

// ---------------- setup kernels -----------------------------------------------
extern "C" __global__ void __launch_bounds__(128)
k_init() {
    int i = blockIdx.x * blockDim.x + threadIdx.x;
    if (i < N_NODES * HDIM) g_num[i] = 0.0f;
    if (i < N_NODES * NHEADS) g_den[i] = 0.0f;
}

// ALL weight conversions in one launch (block-range table).
extern "C" __global__ void __launch_bounds__(256)
k_wconv_all(const float* __restrict__ Wv1, const float* __restrict__ Wv2,
            const float* __restrict__ Wv3, const float* __restrict__ Wb1,
            const float* __restrict__ Wb2, const float* __restrict__ Wb3) {
    int b = blockIdx.x, tid = threadIdx.x;
    const float* W; __half* out;
    int pad = 128, real = 128, nch, rs, co = 0, lb;
    if (b < 128)      { W = Wv1; out = g_wv1f;  nch = 4; rs = 256; lb = b; }
    else if (b < 192) { W = Wv2; out = g_wv2f;  nch = 2; rs = 128; lb = b - 128; }
    else if (b < 256) { W = Wv3; out = g_wv3f;  nch = 2; rs = 128; lb = b - 192; }
    else if (b < 384) { W = Wb1; out = g_wb1f;  nch = 4; rs = 384; co = 128; lb = b - 256; }
    else if (b < 448) { W = Wb1; out = g_wb1pf; nch = 2; rs = 384; lb = b - 384; }
    else if (b < 512) { W = Wb2; out = g_wb2f;  nch = 2; rs = 128; lb = b - 448; }
    else              { W = Wb3; out = g_wb3f;  nch = 2; rs = 128; pad = 16; real = 4; lb = b - 512; }
    int idx = lb * 256 + tid;
    int tile = pad * 64;
    if (idx >= tile * nch) return;
    int c = idx / tile, rem = idx % tile;
    int n = rem / 64, kk = rem % 64;
    float x = (n < real) ? W[n * rs + co + c * 64 + kk] : 0.0f;
    unsigned sw = sw128((unsigned)(n * 128 + kk * 2));
    out[c * tile + sw / 2] = __float2half_rn(x);
}

template<int K, int XP>
__device__ __forceinline__ void gemm_stage(float acc[64], const float* __restrict__ wrow,
                                           const float* __restrict__ xs) {
#pragma unroll 1
    for (int k = 0; k < K; k += 4) {
        float4 wv = *reinterpret_cast<const float4*>(wrow + k);
#pragma unroll
        for (int e = 0; e < 64; ++e) {
            float4 xv = *reinterpret_cast<const float4*>(xs + e * XP + k);
            acc[e] = fmaf(wv.x, xv.x, acc[e]);
            acc[e] = fmaf(wv.y, xv.y, acc[e]);
            acc[e] = fmaf(wv.z, xv.z, acc[e]);
            acc[e] = fmaf(wv.w, xv.w, acc[e]);
        }
    }
}

// P = hV @ Wb1[:, :128]^T + bb1 via fp16 HMMA (M=128 nodes per CTA)
extern "C" __global__ void __launch_bounds__(256)
k_pre2(const float* __restrict__ hV, const float* __restrict__ bb1) {
    extern __shared__ char sm[];
    uint32_t smb = smem_to_u32(sm);
    int tid = threadIdx.x, wid = tid >> 5, lid = tid & 31;
    int wm = wid & 1, wn = wid >> 1;
    int n0 = blockIdx.x * 128;

    cpa16k(smb + 32768, (const char*)g_wb1pf, tid);
    cpa16k(smb + 49152, (const char*)g_wb1pf + 16384, tid);
    CP_COMMIT();

    const float4* hv4 = reinterpret_cast<const float4*>(hV);
    for (int u = tid; u < 4096; u += 256) {
        int m = u >> 5, q = u & 31;
        int c = q >> 4, q15 = q & 15;
        float4 v = make_float4(0.f, 0.f, 0.f, 0.f);
        if (n0 + m < N_NODES) v = hv4[(size_t)(n0 + m) * 32 + q];
        *(uint2*)(sm + c * 16384 + sw128((unsigned)(m * 128 + q15 * 8))) =
            make_uint2(pack_h2(v.x, v.y), pack_h2(v.z, v.w));
    }
    CP_WAIT0();
    __syncthreads();

    float acc[4][4][4];
    ZERO_ACC(acc);
    chunk_mma(acc, smb,         smb + 32768, wm, wn, lid);
    chunk_mma(acc, smb + 16384, smb + 49152, wm, wn, lid);

#pragma unroll
    for (int ms = 0; ms < 4; ++ms) {
        int r0 = wm * 64 + ms * 16 + (lid >> 2), r1 = r0 + 8;
#pragma unroll
        for (int ns = 0; ns < 4; ++ns) {
            int n = wn * 32 + ns * 8 + (lid & 3) * 2;
            float b0 = bb1[n], b1v = bb1[n + 1];
            if (n0 + r0 < N_NODES) {
                g_P[(size_t)(n0 + r0) * 128 + n]     = acc[ms][ns][0] + b0;
                g_P[(size_t)(n0 + r0) * 128 + n + 1] = acc[ms][ns][1] + b1v;
            }
            if (n0 + r1 < N_NODES) {
                g_P[(size_t)(n0 + r1) * 128 + n]     = acc[ms][ns][2] + b0;
                g_P[(size_t)(n0 + r1) * 128 + n + 1] = acc[ms][ns][3] + b1v;
            }
        }
    }
}

// ---------------- edge kernel (two-pass, fp16, 2 CTAs/SM, inline hE convert) ----
// mode 1 = bias MLP (-> g_ew, g_den); mode 0 = value MLP (-> scatter g_num)
extern "C" __global__ void __launch_bounds__(256, 2)
k_edge(int mode, const float* __restrict__ hE, const int* __restrict__ cid,
       const float* __restrict__ b1, const float* __restrict__ b2,
       const float* __restrict__ b3) {
    extern __shared__ char sm[];
    uint32_t smb = smem_to_u32(sm);
    int tid = threadIdx.x, wid = tid >> 5, lid = tid & 31;
    int wm = wid & 1, wn = wid >> 1;
    size_t e0 = (size_t)blockIdx.x * 128;
    int* ce = (int*)(sm + OFF_CE);
    float* sew = (float*)(sm + OFF_SEW);
    if (tid < 128) ce[tid] = (e0 + tid < N_EDGES) ? cid[e0 + tid] : 0;

    const char* W1 = (const char*)(mode ? g_wb1f : g_wv1f);
    const char* W2 = (const char*)(mode ? g_wb2f : g_wv2f);
    const uint32_t B0 = smb + OFF_B0, B1 = smb + OFF_B1;
    const uint32_t S  = smb + OFF_S;
    const uint32_t T  = smb + OFF_T;

    float acc[4][4][4];
    ZERO_ACC(acc);

    // ---- L1: hE @ W1^T (K=256, 4 chunks; raw fp32 staged + converted inline) ----
    cpa32k(S, hE, e0, 0, tid);
    cpa16k(B0, W1, tid);
    cpa16k(B1, W1 + 16384, tid);
    CP_COMMIT();                                               // G1: c0 + W1_0 + W1_1
    CP_WAIT0(); __syncthreads();
    conv_tile(sm, OFF_S, OFF_T, tid);                          // c0 -> T0
    __syncthreads();
    cpa32k(S, hE, e0, 1, tid); CP_COMMIT();                    // G2: c1
    chunk_mma(acc, T, B0, wm, wn, lid);
    __syncthreads();
    cpa16k(B0, W1 + 32768, tid); CP_COMMIT();                  // G3: W1_2
    CP_WAIT1(); __syncthreads();                               // G2 done
    conv_tile(sm, OFF_S, OFF_T + 16384, tid);                  // c1 -> T1
    __syncthreads();
    cpa32k(S, hE, e0, 2, tid); CP_COMMIT();                    // G4: c2
    chunk_mma(acc, T + 16384, B1, wm, wn, lid);
    __syncthreads();
    cpa16k(B1, W1 + 49152, tid); CP_COMMIT();                  // G5: W1_3
    CP_WAIT1(); __syncthreads();                               // G3,G4 done
    conv_tile(sm, OFF_S, OFF_T, tid);                          // c2 -> T0
    __syncthreads();
    cpa32k(S, hE, e0, 3, tid); CP_COMMIT();                    // G6: c3
    chunk_mma(acc, T, B0, wm, wn, lid);
    __syncthreads();
    cpa16k(B0, W2, tid); CP_COMMIT();                          // G7: W2_0
    CP_WAIT1(); __syncthreads();                               // G5,G6 done
    conv_tile(sm, OFF_S, OFF_T + 16384, tid);                  // c3 -> T1
    __syncthreads();
    chunk_mma(acc, T + 16384, B1, wm, wn, lid);
    __syncthreads();
    cpa16k(B1, W2 + 16384, tid); CP_COMMIT();                  // G8: W2_1
    // t1 = gelu(D + (P[ce] | bv1)) -> T (A tiles dead)
    epi_store(acc, sm + OFF_T, mode ? g_P : b1, ce, mode != 0, wm, wn, lid);
    __syncthreads();

    // ---- L2: t1 @ W2^T ----
    ZERO_ACC(acc);
    CP_WAIT1(); __syncthreads();                               // G7 done
    chunk_mma(acc, T, B0, wm, wn, lid);
    CP_WAIT0(); __syncthreads();                               // G8 done
    chunk_mma(acc, T + 16384, B1, wm, wn, lid);
    __syncthreads();

    // ---- L3 ----
    if (mode) {
        // Wb3 (4KB) -> B0, overlapped with t2 epilogue
        cp16(B0 + tid * 16, (const char*)g_wb3f + tid * 16);
        CP_COMMIT();
        epi_store(acc, sm + OFF_T, b2, ce, false, wm, wn, lid);   // t2 -> T
        __syncthreads();
        CP_WAIT0(); __syncthreads();
        float accl[4][4];
#pragma unroll
        for (int i = 0; i < 4; ++i)
#pragma unroll
            for (int k = 0; k < 4; ++k) accl[i][k] = 0.f;
        if (wn == 0) {
            chunk_mma_log(accl, T, B0, wm, lid);
            chunk_mma_log(accl, T + 16384, B0 + 2048, wm, lid);
        }
        if (wn == 0 && (lid & 3) < 2) {
            const float rs = 0.17677669529663687f;  // 1/sqrt(32)
            int n = (lid & 3) * 2;
            float bn0 = b3[n], bn1 = b3[n + 1];
#pragma unroll
            for (int ms = 0; ms < 4; ++ms) {
                int r0 = wm * 64 + ms * 16 + (lid >> 2), r1 = r0 + 8;
                float w0 = __expf((accl[ms][0] + bn0) * rs);
                float w1 = __expf((accl[ms][1] + bn1) * rs);
                float w2 = __expf((accl[ms][2] + bn0) * rs);
                float w3 = __expf((accl[ms][3] + bn1) * rs);
                g_ew[(e0 + r0) * 4 + n] = w0;
                g_ew[(e0 + r0) * 4 + n + 1] = w1;
                g_ew[(e0 + r1) * 4 + n] = w2;
                g_ew[(e0 + r1) * 4 + n + 1] = w3;
                if (e0 + r0 < N_EDGES)
                    red2(&g_den[(size_t)ce[r0] * 4 + n], w0, w1);
                if (e0 + r1 < N_EDGES)
                    red2(&g_den[(size_t)ce[r1] * 4 + n], w2, w3);
            }
        }
    } else {
        // Wv3 loads overlapped with t2 epilogue + ew fetch
        cpa16k(B0, (const char*)g_wv3f, tid);
        CP_COMMIT();                                            // Ga
        cpa16k(B1, (const char*)g_wv3f + 16384, tid);
        CP_COMMIT();                                            // Gb
        epi_store(acc, sm + OFF_T, b2, ce, false, wm, wn, lid);    // t2 -> T
        if (tid < 128)
            *(float4*)(sew + tid * 4) = *(const float4*)(g_ew + (e0 + tid) * 4);
        __syncthreads();
        ZERO_ACC(acc);
        CP_WAIT1(); __syncthreads();                            // Ga done
        chunk_mma(acc, T, B0, wm, wn, lid);
        CP_WAIT0(); __syncthreads();                            // Gb done
        chunk_mma(acc, T + 16384, B1, wm, wn, lid);

        // scatter: lane-pair shuffle -> 16B red.v4 (even lanes: r0, odd: r1)
        int odd = lid & 1;
#pragma unroll
        for (int ms = 0; ms < 4; ++ms) {
            int r0 = wm * 64 + ms * 16 + (lid >> 2), r1 = r0 + 8;
            float ew0 = sew[r0 * 4 + wn], ew1 = sew[r1 * 4 + wn];
            bool v0 = (e0 + r0) < N_EDGES, v1 = (e0 + r1) < N_EDGES;
            float* d0 = g_num + (size_t)ce[r0] * 128;
            float* d1 = g_num + (size_t)ce[r1] * 128;
#pragma unroll
            for (int ns = 0; ns < 4; ++ns) {
                int n = wn * 32 + ns * 8 + (lid & 3) * 2;
                float b0 = b3[n], b1v = b3[n + 1];
                float x0 = acc[ms][ns][0] + b0, x1 = acc[ms][ns][1] + b1v;
                float x2 = acc[ms][ns][2] + b0, x3 = acc[ms][ns][3] + b1v;
                float s0 = __shfl_xor_sync(0xffffffffu, odd ? x0 : x2, 1);
                float s1 = __shfl_xor_sync(0xffffffffu, odd ? x1 : x3, 1);
                if (!odd) {
                    if (v0) red4(d0 + n, ew0 * x0, ew0 * x1, ew0 * s0, ew0 * s1);
                } else {
                    if (v1) red4(d1 + n - 2, ew1 * s0, ew1 * s1, ew1 * x2, ew1 * x3);
                }
            }
        }
    }
}

// ---------------- output projection --------------------------------------------
extern "C" __global__ void __launch_bounds__(128)
k_out(const float* __restrict__ Wo, float* __restrict__ out) {
    __shared__ float xs[64 * HDIM];
    int j = threadIdx.x;
    int n0 = blockIdx.x * 64;
    int cnt = N_NODES - n0; if (cnt > 64) cnt = 64;
    for (int i = j; i < 64 * HDIM; i += 128) {
        int n = i >> 7, c = i & 127;
        float v = 0.f;
        if (n < cnt) {
            float d = g_den[(size_t)(n0 + n) * NHEADS + (c >> 5)];
            float nm = g_num[(size_t)(n0 + n) * HDIM + c];
            v = (d > 0.f) ? nm / d : 0.f;
        }
        xs[i] = v;
    }
    __syncthreads();
    float acc[64];
#pragma unroll
    for (int e = 0; e < 64; ++e) acc[e] = 0.f;
    gemm_stage<HDIM, HDIM>(acc, Wo + j * HDIM, xs);
#pragma unroll
    for (int e = 0; e < 64; ++e)
        if (e < cnt) out[(size_t)(n0 + e) * HDIM + j] = acc[e];
}

// ---------------- launch --------------------------------------------------------
extern "C" void kernel_launch(void* const* d_in, const int* in_sizes, int n_in,
                              void* d_out, int out_size) {
    const float* hV  = (const float*)d_in[0];
    const float* hE  = (const float*)d_in[1];
    const float* Wv1 = (const float*)d_in[2];
    const float* bv1 = (const float*)d_in[3];
    const float* Wv2 = (const float*)d_in[4];
    const float* bv2 = (const float*)d_in[5];
    const float* Wv3 = (const float*)d_in[6];
    const float* bv3 = (const float*)d_in[7];
    const float* Wb1 = (const float*)d_in[8];
    const float* bb1 = (const float*)d_in[9];
    const float* Wb2 = (const float*)d_in[10];
    const float* bb2 = (const float*)d_in[11];
    const float* Wb3 = (const float*)d_in[12];
    const float* bb3 = (const float*)d_in[13];
    const float* Wo  = (const float*)d_in[14];
    const int*   cid = (const int*)d_in[15];
    float* out = (float*)d_out;

    cudaFuncSetAttribute(k_edge, cudaFuncAttributeMaxDynamicSharedMemorySize, SMEM_E);
    cudaFuncSetAttribute(k_pre2, cudaFuncAttributeMaxDynamicSharedMemorySize, SMEM_P);

    // [0] k_init [1] k_wconv_all [2] k_pre2 [3] k_init (filler, idempotent)
    // [4] k_edge(bias) [5] k_edge(value) <- ncu -s 5 profiles this  [6] k_out
    k_init<<<(N_NODES * HDIM + 127) / 128, 128>>>();
    k_wconv_all<<<520, 256>>>(Wv1, Wv2, Wv3, Wb1, Wb2, Wb3);
    k_pre2<<<(N_NODES + 127) / 128, 256, SMEM_P>>>(hV, bb1);
    k_init<<<(N_NODES * HDIM + 127) / 128, 128>>>();
    k_edge<<<EB, 256, SMEM_E>>>(1, hE, cid, bb1, bb2, bb3);   // bias MLP -> ew, den
    k_edge<<<EB, 256, SMEM_E>>>(0, hE, cid, bv1, bv2, bv3);   // value MLP -> num
    k_out<<<(N_NODES + 63) / 64, 128>>>(Wo, out);
}

// round 16
// speedup vs baseline: 1.0996x; 1.0996x over previous
#include <cuda_runtime.h>
#include <cuda_fp16.h>
#include <math.h>
#include <cstdint>

#define N_NODES 20000
#define N_EDGES 600000
#define HDIM 128
#define NHEADS 4
#define EB 4688   // ceil(600000/128)

// ---------------- scratch -----------------------------------------------------
__device__ float g_P[N_NODES * HDIM];
__device__ float g_num[N_NODES * HDIM];
__device__ float g_den[N_NODES * NHEADS];
__device__ float g_ew[(size_t)EB * 128 * NHEADS];   // padded per-edge exp weights

// pre-converted, pre-swizzled fp16 hE tiles: [block][chunk][16KB]
__device__ __align__(16) char g_hEf[(size_t)EB * 4 * 16384];

__device__ __align__(16) __half g_wv1f[32768];
__device__ __align__(16) __half g_wv2f[16384];
__device__ __align__(16) __half g_wv3f[16384];
__device__ __align__(16) __half g_wb1f[32768];
__device__ __align__(16) __half g_wb1pf[16384];   // Wb1[:, :128] (node half) for k_pre2
__device__ __align__(16) __half g_wb2f[16384];
__device__ __align__(16) __half g_wb3f[2048];
__device__ __align__(16) __half g_wof[16384];     // Wo for k_out2

// ---------------- helpers -----------------------------------------------------
__device__ __forceinline__ float gelu_f(float x) {
    return 0.5f * x * (1.0f + erff(x * 0.70710678118654752440f));
}
__device__ __forceinline__ uint32_t smem_to_u32(const void* p) {
    uint32_t a;
    asm("{ .reg .u64 t; cvta.to.shared.u64 t, %1; cvt.u32.u64 %0, t; }" : "=r"(a) : "l"(p));
    return a;
}
__device__ __forceinline__ unsigned sw128(unsigned byte) {
    return byte ^ ((byte >> 3) & 0x70);
}
__device__ __forceinline__ unsigned pack_h2(float a, float b) {
    __half2 h = __floats2half2_rn(a, b);
    return *reinterpret_cast<unsigned*>(&h);
}
// vectorized global reductions (base PTX, sm_90+)
__device__ __forceinline__ void red2(float* addr, float a, float b) {
    asm volatile("red.global.add.v2.f32 [%0], {%1, %2};"
                 :: "l"(addr), "f"(a), "f"(b) : "memory");
}
__device__ __forceinline__ void red4(float* addr, float a, float b, float c, float d) {
    asm volatile("red.global.add.v4.f32 [%0], {%1, %2, %3, %4};"
                 :: "l"(addr), "f"(a), "f"(b), "f"(c), "f"(d) : "memory");
}

// ---------------- cp.async ------------------------------------------------------
__device__ __forceinline__ void cp16(uint32_t dst, const void* src) {
    asm volatile("cp.async.cg.shared.global [%0], [%1], 16;" :: "r"(dst), "l"(src));
}
#define CP_COMMIT() asm volatile("cp.async.commit_group;" ::: "memory")
#define CP_WAIT0()  asm volatile("cp.async.wait_group 0;" ::: "memory")
#define CP_WAIT1()  asm volatile("cp.async.wait_group 1;" ::: "memory")

__device__ __forceinline__ void cpa16k(uint32_t dst, const char* src, int tid) {
#pragma unroll
    for (int j = 0; j < 4; ++j)
        cp16(dst + tid * 16 + j * 4096, src + tid * 16 + j * 4096);
}

// ---------------- mma.sync primitives ------------------------------------------
__device__ __forceinline__ void ldsm4(unsigned r[4], uint32_t addr) {
    asm volatile("ldmatrix.sync.aligned.m8n8.x4.shared.b16 {%0,%1,%2,%3}, [%4];"
        : "=r"(r[0]), "=r"(r[1]), "=r"(r[2]), "=r"(r[3]) : "r"(addr));
}
__device__ __forceinline__ void mma_f16(float c[4], const unsigned a[4], const unsigned b[2]) {
    asm volatile("mma.sync.aligned.m16n8k16.row.col.f32.f16.f16.f32 "
        "{%0,%1,%2,%3}, {%4,%5,%6,%7}, {%8,%9}, {%0,%1,%2,%3};"
        : "+f"(c[0]), "+f"(c[1]), "+f"(c[2]), "+f"(c[3])
        : "r"(a[0]), "r"(a[1]), "r"(a[2]), "r"(a[3]), "r"(b[0]), "r"(b[1]));
}

// smem byte offsets (total 102400 -> 2 CTAs/SM)
#define OFF_CE   0
#define OFF_SEW  512
#define OFF_B0   4096
#define OFF_B1   20480
#define OFF_A0   36864
#define OFF_A1   53248
#define OFF_T    69632      /* 2 chunks x 16KB */
#define SMEM_E   102400
#define SMEM_P   65536

// one K=64 chunk, single fp16 pass; tiles 128x64 fp16 SW128 (128B pitch)
__device__ __forceinline__ void chunk_mma(float acc[4][4][4],
                                          uint32_t A, uint32_t B,
                                          int wm, int wn, int lid) {
    int g = lid >> 3, r = lid & 7;
    int am = (g & 1) * 8 + r, ak = (g >> 1) * 8;
    int bn = (g >> 1) * 8 + r, bk = (g & 1) * 8;
#pragma unroll
    for (int ks = 0; ks < 4; ++ks) {
        int kb = ks * 16;
        unsigned Af[4][4], Bf[4][2];
#pragma unroll
        for (int ms = 0; ms < 4; ++ms) {
            unsigned byte = (unsigned)((wm * 64 + ms * 16 + am) * 128 + (kb + ak) * 2);
            ldsm4(Af[ms], A + sw128(byte));
        }
#pragma unroll
        for (int np = 0; np < 2; ++np) {
            unsigned byte = (unsigned)((wn * 32 + np * 16 + bn) * 128 + (kb + bk) * 2);
            unsigned t[4];
            ldsm4(t, B + sw128(byte));
            Bf[np*2][0] = t[0]; Bf[np*2][1] = t[1];
            Bf[np*2+1][0] = t[2]; Bf[np*2+1][1] = t[3];
        }
#pragma unroll
        for (int ms = 0; ms < 4; ++ms)
#pragma unroll
            for (int ns = 0; ns < 4; ++ns)
                mma_f16(acc[ms][ns], Af[ms], Bf[ns]);
    }
}

// logits variant: n0-7 only, B tile 16-row padded (2KB per chunk)
__device__ __forceinline__ void chunk_mma_log(float accl[4][4],
                                              uint32_t A, uint32_t B,
                                              int wm, int lid) {
    int g = lid >> 3, r = lid & 7;
    int am = (g & 1) * 8 + r, ak = (g >> 1) * 8;
    int bn = (g >> 1) * 8 + r, bk = (g & 1) * 8;
#pragma unroll
    for (int ks = 0; ks < 4; ++ks) {
        int kb = ks * 16;
        unsigned Af[4][4], Bf[2];
#pragma unroll
        for (int ms = 0; ms < 4; ++ms) {
            unsigned byte = (unsigned)((wm * 64 + ms * 16 + am) * 128 + (kb + ak) * 2);
            ldsm4(Af[ms], A + sw128(byte));
        }
        unsigned byte = (unsigned)(bn * 128 + (kb + bk) * 2);
        unsigned t[4];
        ldsm4(t, B + sw128(byte));
        Bf[0] = t[0]; Bf[1] = t[1];
#pragma unroll
        for (int ms = 0; ms < 4; ++ms)
            mma_f16(accl[ms], Af[ms], Bf);
    }
}

// acc + add -> gelu -> fp16 -> T tiles (chunk ch @ +ch*16K)
__device__ __forceinline__ void epi_store(float acc[4][4][4], char* T,
                                          const float* __restrict__ addv,
                                          const int* __restrict__ ce, bool perrow,
                                          int wm, int wn, int lid) {
#pragma unroll
    for (int ms = 0; ms < 4; ++ms) {
        int r0 = wm * 64 + ms * 16 + (lid >> 2), r1 = r0 + 8;
#pragma unroll
        for (int ns = 0; ns < 4; ++ns) {
            int n = wn * 32 + ns * 8 + (lid & 3) * 2;
            const float* a0 = perrow ? (addv + (size_t)ce[r0] * 128 + n) : (addv + n);
            const float* a1 = perrow ? (addv + (size_t)ce[r1] * 128 + n) : (addv + n);
            float o0 = gelu_f(acc[ms][ns][0] + a0[0]);
            float o1 = gelu_f(acc[ms][ns][1] + a0[1]);
            float o2 = gelu_f(acc[ms][ns][2] + a1[0]);
            float o3 = gelu_f(acc[ms][ns][3] + a1[1]);
            int ch = n >> 6, kk = n & 63;
            char* th = T + ch * 16384;
            *(unsigned*)(th + sw128((unsigned)(r0 * 128 + kk * 2))) = pack_h2(o0, o1);
            *(unsigned*)(th + sw128((unsigned)(r1 * 128 + kk * 2))) = pack_h2(o2, o3);
        }
    }
}

#define ZERO_ACC(acc) do {                                                    \
    _Pragma("unroll") for (int _i = 0; _i < 4; ++_i)                          \
    _Pragma("unroll") for (int _j = 0; _j < 4; ++_j)                          \
    _Pragma("unroll") for (int _k = 0; _k < 4; ++_k) (acc)[_i][_j][_k] = 0.f; \
} while (0)

// ---------------- setup kernels -----------------------------------------------
// ALL weight conversions in one launch (block-range table).
// Ranges: [0,128) Wv1 | [128,192) Wv2 | [192,256) Wv3 | [256,384) Wb1e |
//         [384,448) Wb1p | [448,512) Wb2 | [512,520) Wb3 | [520,584) Wo
extern "C" __global__ void __launch_bounds__(256)
k_wconv_all(const float* __restrict__ Wv1, const float* __restrict__ Wv2,
            const float* __restrict__ Wv3, const float* __restrict__ Wb1,
            const float* __restrict__ Wb2, const float* __restrict__ Wb3,
            const float* __restrict__ Wo) {
    int b = blockIdx.x, tid = threadIdx.x;
    const float* W; __half* out;
    int pad = 128, real = 128, nch, rs, co = 0, lb;
    if (b < 128)      { W = Wv1; out = g_wv1f;  nch = 4; rs = 256; lb = b; }
    else if (b < 192) { W = Wv2; out = g_wv2f;  nch = 2; rs = 128; lb = b - 128; }
    else if (b < 256) { W = Wv3; out = g_wv3f;  nch = 2; rs = 128; lb = b - 192; }
    else if (b < 384) { W = Wb1; out = g_wb1f;  nch = 4; rs = 384; co = 128; lb = b - 256; }
    else if (b < 448) { W = Wb1; out = g_wb1pf; nch = 2; rs = 384; lb = b - 384; }
    else if (b < 512) { W = Wb2; out = g_wb2f;  nch = 2; rs = 128; lb = b - 448; }
    else if (b < 520) { W = Wb3; out = g_wb3f;  nch = 2; rs = 128; pad = 16; real = 4; lb = b - 512; }
    else              { W = Wo;  out = g_wof;   nch = 2; rs = 128; lb = b - 520; }
    int idx = lb * 256 + tid;
    int tile = pad * 64;
    if (idx >= tile * nch) return;
    int c = idx / tile, rem = idx % tile;
    int n = rem / 64, kk = rem % 64;
    float x = (n < real) ? W[n * rs + co + c * 64 + kk] : 0.0f;
    unsigned sw = sw128((unsigned)(n * 128 + kk * 2));
    out[c * tile + sw / 2] = __float2half_rn(x);
}

// hE -> pre-swizzled fp16 tiles; each thread emits one 16B store (full sector)
extern "C" __global__ void __launch_bounds__(256)
k_econv(const float* __restrict__ hE) {
    const float4* hE4 = reinterpret_cast<const float4*>(hE);
    const size_t total = (size_t)EB * 128 * 32;   // 16B units
#pragma unroll
    for (int j = 0; j < 4; ++j) {
        size_t idx = (size_t)blockIdx.x * 1024 + j * 256 + threadIdx.x;
        if (idx >= total) continue;
        size_t e = idx >> 5; int qp = (int)(idx & 31);
        int q = qp * 2;
        int c = q >> 4, q15 = q & 15;
        int m = (int)(e & 127); size_t eb = e >> 7;
        float4 v0 = make_float4(0.f, 0.f, 0.f, 0.f), v1 = v0;
        if (e < N_EDGES) {
            v0 = hE4[e * 64 + (size_t)q];
            v1 = hE4[e * 64 + (size_t)q + 1];
        }
        unsigned sw = sw128((unsigned)(m * 128 + q15 * 8));
        size_t tb = (eb * 4 + (size_t)c) * 16384;
        *(uint4*)(g_hEf + tb + sw) = make_uint4(pack_h2(v0.x, v0.y), pack_h2(v0.z, v0.w),
                                                pack_h2(v1.x, v1.y), pack_h2(v1.z, v1.w));
    }
}

// P = hV @ Wb1[:, :128]^T + bb1 via fp16 HMMA (M=128 nodes per CTA)
extern "C" __global__ void __launch_bounds__(256)
k_pre2(const float* __restrict__ hV, const float* __restrict__ bb1) {
    extern __shared__ char sm[];
    uint32_t smb = smem_to_u32(sm);
    int tid = threadIdx.x, wid = tid >> 5, lid = tid & 31;
    int wm = wid & 1, wn = wid >> 1;
    int n0 = blockIdx.x * 128;

    cpa16k(smb + 32768, (const char*)g_wb1pf, tid);
    cpa16k(smb + 49152, (const char*)g_wb1pf + 16384, tid);
    CP_COMMIT();

    const float4* hv4 = reinterpret_cast<const float4*>(hV);
    for (int u = tid; u < 4096; u += 256) {
        int m = u >> 5, q = u & 31;
        int c = q >> 4, q15 = q & 15;
        float4 v = make_float4(0.f, 0.f, 0.f, 0.f);
        if (n0 + m < N_NODES) v = hv4[(size_t)(n0 + m) * 32 + q];
        *(uint2*)(sm + c * 16384 + sw128((unsigned)(m * 128 + q15 * 8))) =
            make_uint2(pack_h2(v.x, v.y), pack_h2(v.z, v.w));
    }
    CP_WAIT0();
    __syncthreads();

    float acc[4][4][4];
    ZERO_ACC(acc);
    chunk_mma(acc, smb,         smb + 32768, wm, wn, lid);
    chunk_mma(acc, smb + 16384, smb + 49152, wm, wn, lid);

#pragma unroll
    for (int ms = 0; ms < 4; ++ms) {
        int r0 = wm * 64 + ms * 16 + (lid >> 2), r1 = r0 + 8;
#pragma unroll
        for (int ns = 0; ns < 4; ++ns) {
            int n = wn * 32 + ns * 8 + (lid & 3) * 2;
            float b0 = bb1[n], b1v = bb1[n + 1];
            if (n0 + r0 < N_NODES) {
                g_P[(size_t)(n0 + r0) * 128 + n]     = acc[ms][ns][0] + b0;
                g_P[(size_t)(n0 + r0) * 128 + n + 1] = acc[ms][ns][1] + b1v;
            }
            if (n0 + r1 < N_NODES) {
                g_P[(size_t)(n0 + r1) * 128 + n]     = acc[ms][ns][2] + b0;
                g_P[(size_t)(n0 + r1) * 128 + n + 1] = acc[ms][ns][3] + b1v;
            }
        }
    }
}

// ---------------- edge kernel (two-pass, fp16, 2 CTAs/SM) ----------------------
// mode 1 = bias MLP (-> g_ew, g_den); mode 0 = value MLP (-> scatter g_num)
extern "C" __global__ void __launch_bounds__(256, 2)
k_edge(int mode, const int* __restrict__ cid,
       const float* __restrict__ b1, const float* __restrict__ b2,
       const float* __restrict__ b3) {
    extern __shared__ char sm[];
    uint32_t smb = smem_to_u32(sm);
    int tid = threadIdx.x, wid = tid >> 5, lid = tid & 31;
    int wm = wid & 1, wn = wid >> 1;
    size_t e0 = (size_t)blockIdx.x * 128;
    size_t eb = (size_t)blockIdx.x;
    int* ce = (int*)(sm + OFF_CE);
    float* sew = (float*)(sm + OFF_SEW);
    if (tid < 128) ce[tid] = (e0 + tid < N_EDGES) ? cid[e0 + tid] : 0;

    const char* W1 = (const char*)(mode ? g_wb1f : g_wv1f);
    const char* W2 = (const char*)(mode ? g_wb2f : g_wv2f);
    const uint32_t A0 = smb + OFF_A0, A1 = smb + OFF_A1;
    const uint32_t B0 = smb + OFF_B0, B1 = smb + OFF_B1;
    const uint32_t T  = smb + OFF_T;

    float acc[4][4][4];
    ZERO_ACC(acc);

    // ---- L1: hE @ W1^T (K=256, 4 chunks, double-buffered) ----
    cpa16k(A0, g_hEf + eb * 4 * 16384, tid);
    cpa16k(B0, W1, tid);
    CP_COMMIT();                                               // G1
    cpa16k(A1, g_hEf + (eb * 4 + 1) * 16384, tid);
    cpa16k(B1, W1 + 16384, tid);
    CP_COMMIT();                                               // G2
    CP_WAIT1(); __syncthreads();                               // G1 done
    chunk_mma(acc, A0, B0, wm, wn, lid);
    __syncthreads();
    cpa16k(A0, g_hEf + (eb * 4 + 2) * 16384, tid);
    cpa16k(B0, W1 + 32768, tid);
    CP_COMMIT();                                               // G3
    CP_WAIT1(); __syncthreads();                               // G2 done
    chunk_mma(acc, A1, B1, wm, wn, lid);
    __syncthreads();
    cpa16k(A1, g_hEf + (eb * 4 + 3) * 16384, tid);
    cpa16k(B1, W1 + 49152, tid);
    CP_COMMIT();                                               // G4
    CP_WAIT1(); __syncthreads();                               // G3 done
    chunk_mma(acc, A0, B0, wm, wn, lid);
    __syncthreads();
    cpa16k(B0, W2, tid);
    CP_COMMIT();                                               // G5
    CP_WAIT1(); __syncthreads();                               // G4 done
    chunk_mma(acc, A1, B1, wm, wn, lid);
    __syncthreads();
    cpa16k(B1, W2 + 16384, tid);
    CP_COMMIT();                                               // G6
    // t1 = gelu(D + (P[ce] | bv1)) -> T
    epi_store(acc, sm + OFF_T, mode ? g_P : b1, ce, mode != 0, wm, wn, lid);
    __syncthreads();

    // ---- L2: t1 @ W2^T ----
    ZERO_ACC(acc);
    CP_WAIT1(); __syncthreads();                               // G5 done
    chunk_mma(acc, T, B0, wm, wn, lid);
    CP_WAIT0(); __syncthreads();                               // G6 done
    chunk_mma(acc, T + 16384, B1, wm, wn, lid);
    __syncthreads();

    // ---- L3 ----
    if (mode) {
        // Wb3 (4KB) -> B0, overlapped with t2 epilogue
        cp16(B0 + tid * 16, (const char*)g_wb3f + tid * 16);
        CP_COMMIT();
        epi_store(acc, sm + OFF_T, b2, ce, false, wm, wn, lid);   // t2 -> T
        __syncthreads();
        CP_WAIT0(); __syncthreads();
        float accl[4][4];
#pragma unroll
        for (int i = 0; i < 4; ++i)
#pragma unroll
            for (int k = 0; k < 4; ++k) accl[i][k] = 0.f;
        if (wn == 0) {
            chunk_mma_log(accl, T, B0, wm, lid);
            chunk_mma_log(accl, T + 16384, B0 + 2048, wm, lid);
        }
        if (wn == 0 && (lid & 3) < 2) {
            const float rs = 0.17677669529663687f;  // 1/sqrt(32)
            int n = (lid & 3) * 2;
            float bn0 = b3[n], bn1 = b3[n + 1];
#pragma unroll
            for (int ms = 0; ms < 4; ++ms) {
                int r0 = wm * 64 + ms * 16 + (lid >> 2), r1 = r0 + 8;
                float w0 = __expf((accl[ms][0] + bn0) * rs);
                float w1 = __expf((accl[ms][1] + bn1) * rs);
                float w2 = __expf((accl[ms][2] + bn0) * rs);
                float w3 = __expf((accl[ms][3] + bn1) * rs);
                g_ew[(e0 + r0) * 4 + n] = w0;
                g_ew[(e0 + r0) * 4 + n + 1] = w1;
                g_ew[(e0 + r1) * 4 + n] = w2;
                g_ew[(e0 + r1) * 4 + n + 1] = w3;
                if (e0 + r0 < N_EDGES)
                    red2(&g_den[(size_t)ce[r0] * 4 + n], w0, w1);
                if (e0 + r1 < N_EDGES)
                    red2(&g_den[(size_t)ce[r1] * 4 + n], w2, w3);
            }
        }
    } else {
        // Wv3 loads overlapped with t2 epilogue + ew fetch
        cpa16k(B0, (const char*)g_wv3f, tid);
        CP_COMMIT();                                            // G7
        cpa16k(B1, (const char*)g_wv3f + 16384, tid);
        CP_COMMIT();                                            // G8
        epi_store(acc, sm + OFF_T, b2, ce, false, wm, wn, lid);    // t2 -> T
        if (tid < 128)
            *(float4*)(sew + tid * 4) = *(const float4*)(g_ew + (e0 + tid) * 4);
        __syncthreads();
        ZERO_ACC(acc);
        CP_WAIT1(); __syncthreads();                            // G7 done
        chunk_mma(acc, T, B0, wm, wn, lid);
        CP_WAIT0(); __syncthreads();                            // G8 done
        chunk_mma(acc, T + 16384, B1, wm, wn, lid);

        // scatter: lane-pair shuffle -> 16B red.v4 (even lanes: r0, odd: r1)
        int odd = lid & 1;
#pragma unroll
        for (int ms = 0; ms < 4; ++ms) {
            int r0 = wm * 64 + ms * 16 + (lid >> 2), r1 = r0 + 8;
            float ew0 = sew[r0 * 4 + wn], ew1 = sew[r1 * 4 + wn];
            bool v0 = (e0 + r0) < N_EDGES, v1 = (e0 + r1) < N_EDGES;
            float* d0 = g_num + (size_t)ce[r0] * 128;
            float* d1 = g_num + (size_t)ce[r1] * 128;
#pragma unroll
            for (int ns = 0; ns < 4; ++ns) {
                int n = wn * 32 + ns * 8 + (lid & 3) * 2;
                float b0 = b3[n], b1v = b3[n + 1];
                float x0 = acc[ms][ns][0] + b0, x1 = acc[ms][ns][1] + b1v;
                float x2 = acc[ms][ns][2] + b0, x3 = acc[ms][ns][3] + b1v;
                float s0 = __shfl_xor_sync(0xffffffffu, odd ? x0 : x2, 1);
                float s1 = __shfl_xor_sync(0xffffffffu, odd ? x1 : x3, 1);
                if (!odd) {
                    if (v0) red4(d0 + n, ew0 * x0, ew0 * x1, ew0 * s0, ew0 * s1);
                } else {
                    if (v1) red4(d1 + n - 2, ew1 * s0, ew1 * s1, ew1 * x2, ew1 * x3);
                }
            }
        }
    }
}

// ---------------- output projection via HMMA ------------------------------------
// out = (num/den) @ Wo^T ; M=128 nodes per CTA, same structure as k_pre2
extern "C" __global__ void __launch_bounds__(256)
k_out2(float* __restrict__ out) {
    extern __shared__ char sm[];
    uint32_t smb = smem_to_u32(sm);
    int tid = threadIdx.x, wid = tid >> 5, lid = tid & 31;
    int wm = wid & 1, wn = wid >> 1;
    int n0 = blockIdx.x * 128;

    cpa16k(smb + 32768, (const char*)g_wof, tid);
    cpa16k(smb + 49152, (const char*)g_wof + 16384, tid);
    CP_COMMIT();

    // build normalized agg tile in fp16 (2 chunks)
    for (int u = tid; u < 4096; u += 256) {
        int m = u >> 5, q = u & 31;
        int c = q >> 4, q15 = q & 15;
        float4 v = make_float4(0.f, 0.f, 0.f, 0.f);
        if (n0 + m < N_NODES) {
            v = *(const float4*)(g_num + (size_t)(n0 + m) * 128 + q * 4);
            float d = g_den[(size_t)(n0 + m) * 4 + (q >> 3)];
            float r = (d > 0.f) ? (1.0f / d) : 0.f;
            v.x *= r; v.y *= r; v.z *= r; v.w *= r;
        }
        *(uint2*)(sm + c * 16384 + sw128((unsigned)(m * 128 + q15 * 8))) =
            make_uint2(pack_h2(v.x, v.y), pack_h2(v.z, v.w));
    }
    CP_WAIT0();
    __syncthreads();

    float acc[4][4][4];
    ZERO_ACC(acc);
    chunk_mma(acc, smb,         smb + 32768, wm, wn, lid);
    chunk_mma(acc, smb + 16384, smb + 49152, wm, wn, lid);

#pragma unroll
    for (int ms = 0; ms < 4; ++ms) {
        int r0 = wm * 64 + ms * 16 + (lid >> 2), r1 = r0 + 8;
#pragma unroll
        for (int ns = 0; ns < 4; ++ns) {
            int n = wn * 32 + ns * 8 + (lid & 3) * 2;
            if (n0 + r0 < N_NODES) {
                out[(size_t)(n0 + r0) * 128 + n]     = acc[ms][ns][0];
                out[(size_t)(n0 + r0) * 128 + n + 1] = acc[ms][ns][1];
            }
            if (n0 + r1 < N_NODES) {
                out[(size_t)(n0 + r1) * 128 + n]     = acc[ms][ns][2];
                out[(size_t)(n0 + r1) * 128 + n + 1] = acc[ms][ns][3];
            }
        }
    }
}

// ---------------- launch --------------------------------------------------------
extern "C" void kernel_launch(void* const* d_in, const int* in_sizes, int n_in,
                              void* d_out, int out_size) {
    const float* hV  = (const float*)d_in[0];
    const float* hE  = (const float*)d_in[1];
    const float* Wv1 = (const float*)d_in[2];
    const float* bv1 = (const float*)d_in[3];
    const float* Wv2 = (const float*)d_in[4];
    const float* bv2 = (const float*)d_in[5];
    const float* Wv3 = (const float*)d_in[6];
    const float* bv3 = (const float*)d_in[7];
    const float* Wb1 = (const float*)d_in[8];
    const float* bb1 = (const float*)d_in[9];
    const float* Wb2 = (const float*)d_in[10];
    const float* bb2 = (const float*)d_in[11];
    const float* Wb3 = (const float*)d_in[12];
    const float* bb3 = (const float*)d_in[13];
    const float* Wo  = (const float*)d_in[14];
    const int*   cid = (const int*)d_in[15];
    float* out = (float*)d_out;

    void *numPtr, *denPtr;
    cudaGetSymbolAddress(&numPtr, g_num);
    cudaGetSymbolAddress(&denPtr, g_den);

    cudaFuncSetAttribute(k_edge, cudaFuncAttributeMaxDynamicSharedMemorySize, SMEM_E);
    cudaFuncSetAttribute(k_pre2, cudaFuncAttributeMaxDynamicSharedMemorySize, SMEM_P);
    cudaFuncSetAttribute(k_out2, cudaFuncAttributeMaxDynamicSharedMemorySize, SMEM_P);

    cudaMemsetAsync(numPtr, 0, (size_t)N_NODES * HDIM * sizeof(float));
    cudaMemsetAsync(denPtr, 0, (size_t)N_NODES * NHEADS * sizeof(float));
    k_wconv_all<<<584, 256>>>(Wv1, Wv2, Wv3, Wb1, Wb2, Wb3, Wo);
    k_econv<<<(EB * 128 * 32 + 1023) / 1024, 256>>>(hE);
    k_pre2<<<(N_NODES + 127) / 128, 256, SMEM_P>>>(hV, bb1);
    k_edge<<<EB, 256, SMEM_E>>>(1, cid, bb1, bb2, bb3);   // bias MLP -> ew, den
    k_edge<<<EB, 256, SMEM_E>>>(0, cid, bv1, bv2, bv3);   // value MLP -> num
    k_out2<<<(N_NODES + 127) / 128, 256, SMEM_P>>>(out);
}

// round 17
// speedup vs baseline: 1.1307x; 1.0282x over previous
#include <cuda_runtime.h>
#include <cuda_fp16.h>
#include <math.h>
#include <cstdint>

#define N_NODES 20000
#define N_EDGES 600000
#define HDIM 128
#define NHEADS 4
#define EB 4688   // ceil(600000/128)

// ---------------- scratch -----------------------------------------------------
__device__ float g_P[N_NODES * HDIM];
__device__ float g_num[N_NODES * HDIM];
__device__ float g_den[N_NODES * NHEADS];
__device__ float g_ew[(size_t)EB * 128 * NHEADS];   // padded per-edge exp weights

// pre-converted, pre-swizzled fp16 hE tiles: [block][chunk][16KB]
__device__ __align__(16) char g_hEf[(size_t)EB * 4 * 16384];

__device__ __align__(16) __half g_wv1f[32768];
__device__ __align__(16) __half g_wv2f[16384];
__device__ __align__(16) __half g_wv3f[16384];
__device__ __align__(16) __half g_wb1f[32768];
__device__ __align__(16) __half g_wb1pf[16384];   // Wb1[:, :128] (node half) for k_pre2
__device__ __align__(16) __half g_wb2f[16384];
__device__ __align__(16) __half g_wb3f[2048];
__device__ __align__(16) __half g_wof[16384];     // Wo for k_out2

// ---------------- helpers -----------------------------------------------------
__device__ __forceinline__ float gelu_f(float x) {
    return 0.5f * x * (1.0f + erff(x * 0.70710678118654752440f));
}
__device__ __forceinline__ uint32_t smem_to_u32(const void* p) {
    uint32_t a;
    asm("{ .reg .u64 t; cvta.to.shared.u64 t, %1; cvt.u32.u64 %0, t; }" : "=r"(a) : "l"(p));
    return a;
}
__device__ __forceinline__ unsigned sw128(unsigned byte) {
    return byte ^ ((byte >> 3) & 0x70);
}
__device__ __forceinline__ unsigned pack_h2(float a, float b) {
    __half2 h = __floats2half2_rn(a, b);
    return *reinterpret_cast<unsigned*>(&h);
}
// vectorized global reductions (base PTX, sm_90+)
__device__ __forceinline__ void red2(float* addr, float a, float b) {
    asm volatile("red.global.add.v2.f32 [%0], {%1, %2};"
                 :: "l"(addr), "f"(a), "f"(b) : "memory");
}
__device__ __forceinline__ void red4(float* addr, float a, float b, float c, float d) {
    asm volatile("red.global.add.v4.f32 [%0], {%1, %2, %3, %4};"
                 :: "l"(addr), "f"(a), "f"(b), "f"(c), "f"(d) : "memory");
}

// ---------------- cp.async ------------------------------------------------------
__device__ __forceinline__ void cp16(uint32_t dst, const void* src) {
    asm volatile("cp.async.cg.shared.global [%0], [%1], 16;" :: "r"(dst), "l"(src));
}
#define CP_COMMIT() asm volatile("cp.async.commit_group;" ::: "memory")
#define CP_WAIT0()  asm volatile("cp.async.wait_group 0;" ::: "memory")
#define CP_WAIT1()  asm volatile("cp.async.wait_group 1;" ::: "memory")

__device__ __forceinline__ void cpa16k(uint32_t dst, const char* src, int tid) {
#pragma unroll
    for (int j = 0; j < 4; ++j)
        cp16(dst + tid * 16 + j * 4096, src + tid * 16 + j * 4096);
}

// ---------------- mma.sync primitives ------------------------------------------
__device__ __forceinline__ void ldsm4(unsigned r[4], uint32_t addr) {
    asm volatile("ldmatrix.sync.aligned.m8n8.x4.shared.b16 {%0,%1,%2,%3}, [%4];"
        : "=r"(r[0]), "=r"(r[1]), "=r"(r[2]), "=r"(r[3]) : "r"(addr));
}
__device__ __forceinline__ void mma_f16(float c[4], const unsigned a[4], const unsigned b[2]) {
    asm volatile("mma.sync.aligned.m16n8k16.row.col.f32.f16.f16.f32 "
        "{%0,%1,%2,%3}, {%4,%5,%6,%7}, {%8,%9}, {%0,%1,%2,%3};"
        : "+f"(c[0]), "+f"(c[1]), "+f"(c[2]), "+f"(c[3])
        : "r"(a[0]), "r"(a[1]), "r"(a[2]), "r"(a[3]), "r"(b[0]), "r"(b[1]));
}

// smem byte offsets (total 102400 -> 2 CTAs/SM)
#define OFF_CE   0
#define OFF_SEW  512
#define OFF_B0   4096
#define OFF_B1   20480
#define OFF_A0   36864
#define OFF_A1   53248
#define OFF_T    69632      /* 2 chunks x 16KB */
#define SMEM_E   102400
#define SMEM_P   65536

// one K=64 chunk, fp16; tiles 128x64 SW128 (128B pitch).
// Row low-3-bits == (lid&7) for every operand, so the swizzle XOR is the
// per-thread constant (r<<4) and all ldsm addresses are base+immediate.
__device__ __forceinline__ void chunk_mma(float acc[4][4][4],
                                          uint32_t A, uint32_t B,
                                          int wm, int wn, int lid) {
    int g = lid >> 3, r = lid & 7;
    int rx = r << 4;
    int am = (g & 1) * 8 + r, ak = (g >> 1) * 8;
    int bn = (g >> 1) * 8 + r, bk = (g & 1) * 8;
    uint32_t Abase = A + (unsigned)((wm * 64 + am) * 128);
    uint32_t Bbase = B + (unsigned)((wn * 32 + bn) * 128);
#pragma unroll
    for (int ks = 0; ks < 4; ++ks) {
        uint32_t Aad = Abase + (unsigned)(((ks * 16 + ak) * 2) ^ rx);
        uint32_t Bad = Bbase + (unsigned)(((ks * 16 + bk) * 2) ^ rx);
        unsigned Af[4][4], Bf[4][2];
#pragma unroll
        for (int ms = 0; ms < 4; ++ms)
            ldsm4(Af[ms], Aad + ms * 2048);
#pragma unroll
        for (int np = 0; np < 2; ++np) {
            unsigned t[4];
            ldsm4(t, Bad + np * 2048);
            Bf[np*2][0] = t[0]; Bf[np*2][1] = t[1];
            Bf[np*2+1][0] = t[2]; Bf[np*2+1][1] = t[3];
        }
#pragma unroll
        for (int ms = 0; ms < 4; ++ms)
#pragma unroll
            for (int ns = 0; ns < 4; ++ns)
                mma_f16(acc[ms][ns], Af[ms], Bf[ns]);
    }
}

// logits variant: n0-7 only, B tile 16-row padded (2KB per chunk)
__device__ __forceinline__ void chunk_mma_log(float accl[4][4],
                                              uint32_t A, uint32_t B,
                                              int wm, int lid) {
    int g = lid >> 3, r = lid & 7;
    int rx = r << 4;
    int am = (g & 1) * 8 + r, ak = (g >> 1) * 8;
    int bn = (g >> 1) * 8 + r, bk = (g & 1) * 8;
    uint32_t Abase = A + (unsigned)((wm * 64 + am) * 128);
    uint32_t Bbase = B + (unsigned)(bn * 128);
#pragma unroll
    for (int ks = 0; ks < 4; ++ks) {
        uint32_t Aad = Abase + (unsigned)(((ks * 16 + ak) * 2) ^ rx);
        uint32_t Bad = Bbase + (unsigned)(((ks * 16 + bk) * 2) ^ rx);
        unsigned Af[4][4], Bf[2];
#pragma unroll
        for (int ms = 0; ms < 4; ++ms)
            ldsm4(Af[ms], Aad + ms * 2048);
        unsigned t[4];
        ldsm4(t, Bad);
        Bf[0] = t[0]; Bf[1] = t[1];
#pragma unroll
        for (int ms = 0; ms < 4; ++ms)
            mma_f16(accl[ms], Af[ms], Bf);
    }
}

// acc + add -> gelu -> fp16 -> T tiles (chunk ch @ +ch*16K); same hoisted swizzle
__device__ __forceinline__ void epi_store(float acc[4][4][4], char* T,
                                          const float* __restrict__ addv,
                                          const int* __restrict__ ce, bool perrow,
                                          int wm, int wn, int lid) {
    int rr = lid >> 2;             // 0..7 == row low-3-bits for r0 and r1
    int rx = rr << 4;
#pragma unroll
    for (int ms = 0; ms < 4; ++ms) {
        int r0 = wm * 64 + ms * 16 + rr, r1 = r0 + 8;
#pragma unroll
        for (int ns = 0; ns < 4; ++ns) {
            int n = wn * 32 + ns * 8 + (lid & 3) * 2;
            const float* a0 = perrow ? (addv + (size_t)ce[r0] * 128 + n) : (addv + n);
            const float* a1 = perrow ? (addv + (size_t)ce[r1] * 128 + n) : (addv + n);
            float o0 = gelu_f(acc[ms][ns][0] + a0[0]);
            float o1 = gelu_f(acc[ms][ns][1] + a0[1]);
            float o2 = gelu_f(acc[ms][ns][2] + a1[0]);
            float o3 = gelu_f(acc[ms][ns][3] + a1[1]);
            int ch = n >> 6, kk = n & 63;
            char* th = T + ch * 16384;
            unsigned off = (unsigned)((kk * 2) ^ rx);
            *(unsigned*)(th + r0 * 128 + off) = pack_h2(o0, o1);
            *(unsigned*)(th + r1 * 128 + off) = pack_h2(o2, o3);
        }
    }
}

#define ZERO_ACC(acc) do {                                                    \
    _Pragma("unroll") for (int _i = 0; _i < 4; ++_i)                          \
    _Pragma("unroll") for (int _j = 0; _j < 4; ++_j)                          \
    _Pragma("unroll") for (int _k = 0; _k < 4; ++_k) (acc)[_i][_j][_k] = 0.f; \
} while (0)

// ---------------- setup kernels -----------------------------------------------
// ALL weight conversions in one launch (block-range table).
extern "C" __global__ void __launch_bounds__(256)
k_wconv_all(const float* __restrict__ Wv1, const float* __restrict__ Wv2,
            const float* __restrict__ Wv3, const float* __restrict__ Wb1,
            const float* __restrict__ Wb2, const float* __restrict__ Wb3,
            const float* __restrict__ Wo) {
    int b = blockIdx.x, tid = threadIdx.x;
    const float* W; __half* out;
    int pad = 128, real = 128, nch, rs, co = 0, lb;
    if (b < 128)      { W = Wv1; out = g_wv1f;  nch = 4; rs = 256; lb = b; }
    else if (b < 192) { W = Wv2; out = g_wv2f;  nch = 2; rs = 128; lb = b - 128; }
    else if (b < 256) { W = Wv3; out = g_wv3f;  nch = 2; rs = 128; lb = b - 192; }
    else if (b < 384) { W = Wb1; out = g_wb1f;  nch = 4; rs = 384; co = 128; lb = b - 256; }
    else if (b < 448) { W = Wb1; out = g_wb1pf; nch = 2; rs = 384; lb = b - 384; }
    else if (b < 512) { W = Wb2; out = g_wb2f;  nch = 2; rs = 128; lb = b - 448; }
    else if (b < 520) { W = Wb3; out = g_wb3f;  nch = 2; rs = 128; pad = 16; real = 4; lb = b - 512; }
    else              { W = Wo;  out = g_wof;   nch = 2; rs = 128; lb = b - 520; }
    int idx = lb * 256 + tid;
    int tile = pad * 64;
    if (idx >= tile * nch) return;
    int c = idx / tile, rem = idx % tile;
    int n = rem / 64, kk = rem % 64;
    float x = (n < real) ? W[n * rs + co + c * 64 + kk] : 0.0f;
    unsigned sw = sw128((unsigned)(n * 128 + kk * 2));
    out[c * tile + sw / 2] = __float2half_rn(x);
}

// hE -> pre-swizzled fp16 tiles; each thread emits one 16B store (full sector)
extern "C" __global__ void __launch_bounds__(256)
k_econv(const float* __restrict__ hE) {
    const float4* hE4 = reinterpret_cast<const float4*>(hE);
    const size_t total = (size_t)EB * 128 * 32;   // 16B units
#pragma unroll
    for (int j = 0; j < 4; ++j) {
        size_t idx = (size_t)blockIdx.x * 1024 + j * 256 + threadIdx.x;
        if (idx >= total) continue;
        size_t e = idx >> 5; int qp = (int)(idx & 31);
        int q = qp * 2;
        int c = q >> 4, q15 = q & 15;
        int m = (int)(e & 127); size_t eb = e >> 7;
        float4 v0 = make_float4(0.f, 0.f, 0.f, 0.f), v1 = v0;
        if (e < N_EDGES) {
            v0 = hE4[e * 64 + (size_t)q];
            v1 = hE4[e * 64 + (size_t)q + 1];
        }
        unsigned sw = sw128((unsigned)(m * 128 + q15 * 8));
        size_t tb = (eb * 4 + (size_t)c) * 16384;
        *(uint4*)(g_hEf + tb + sw) = make_uint4(pack_h2(v0.x, v0.y), pack_h2(v0.z, v0.w),
                                                pack_h2(v1.x, v1.y), pack_h2(v1.z, v1.w));
    }
}

// P = hV @ Wb1[:, :128]^T + bb1 via fp16 HMMA (M=128 nodes per CTA)
extern "C" __global__ void __launch_bounds__(256)
k_pre2(const float* __restrict__ hV, const float* __restrict__ bb1) {
    extern __shared__ char sm[];
    uint32_t smb = smem_to_u32(sm);
    int tid = threadIdx.x, wid = tid >> 5, lid = tid & 31;
    int wm = wid & 1, wn = wid >> 1;
    int n0 = blockIdx.x * 128;

    cpa16k(smb + 32768, (const char*)g_wb1pf, tid);
    cpa16k(smb + 49152, (const char*)g_wb1pf + 16384, tid);
    CP_COMMIT();

    const float4* hv4 = reinterpret_cast<const float4*>(hV);
    for (int u = tid; u < 4096; u += 256) {
        int m = u >> 5, q = u & 31;
        int c = q >> 4, q15 = q & 15;
        float4 v = make_float4(0.f, 0.f, 0.f, 0.f);
        if (n0 + m < N_NODES) v = hv4[(size_t)(n0 + m) * 32 + q];
        *(uint2*)(sm + c * 16384 + sw128((unsigned)(m * 128 + q15 * 8))) =
            make_uint2(pack_h2(v.x, v.y), pack_h2(v.z, v.w));
    }
    CP_WAIT0();
    __syncthreads();

    float acc[4][4][4];
    ZERO_ACC(acc);
    chunk_mma(acc, smb,         smb + 32768, wm, wn, lid);
    chunk_mma(acc, smb + 16384, smb + 49152, wm, wn, lid);

#pragma unroll
    for (int ms = 0; ms < 4; ++ms) {
        int r0 = wm * 64 + ms * 16 + (lid >> 2), r1 = r0 + 8;
#pragma unroll
        for (int ns = 0; ns < 4; ++ns) {
            int n = wn * 32 + ns * 8 + (lid & 3) * 2;
            float b0 = bb1[n], b1v = bb1[n + 1];
            if (n0 + r0 < N_NODES) {
                g_P[(size_t)(n0 + r0) * 128 + n]     = acc[ms][ns][0] + b0;
                g_P[(size_t)(n0 + r0) * 128 + n + 1] = acc[ms][ns][1] + b1v;
            }
            if (n0 + r1 < N_NODES) {
                g_P[(size_t)(n0 + r1) * 128 + n]     = acc[ms][ns][2] + b0;
                g_P[(size_t)(n0 + r1) * 128 + n + 1] = acc[ms][ns][3] + b1v;
            }
        }
    }
}

// ---------------- edge kernel (two-pass, fp16, 2 CTAs/SM) ----------------------
// mode 1 = bias MLP (-> g_ew, g_den); mode 0 = value MLP (-> scatter g_num)
extern "C" __global__ void __launch_bounds__(256, 2)
k_edge(int mode, const int* __restrict__ cid,
       const float* __restrict__ b1, const float* __restrict__ b2,
       const float* __restrict__ b3) {
    extern __shared__ char sm[];
    uint32_t smb = smem_to_u32(sm);
    int tid = threadIdx.x, wid = tid >> 5, lid = tid & 31;
    int wm = wid & 1, wn = wid >> 1;
    size_t e0 = (size_t)blockIdx.x * 128;
    size_t eb = (size_t)blockIdx.x;
    int* ce = (int*)(sm + OFF_CE);
    float* sew = (float*)(sm + OFF_SEW);
    if (tid < 128) ce[tid] = (e0 + tid < N_EDGES) ? cid[e0 + tid] : 0;

    const char* W1 = (const char*)(mode ? g_wb1f : g_wv1f);
    const char* W2 = (const char*)(mode ? g_wb2f : g_wv2f);
    const uint32_t A0 = smb + OFF_A0, A1 = smb + OFF_A1;
    const uint32_t B0 = smb + OFF_B0, B1 = smb + OFF_B1;
    const uint32_t T  = smb + OFF_T;

    float acc[4][4][4];
    ZERO_ACC(acc);

    // ---- L1: hE @ W1^T (K=256, 4 chunks, double-buffered) ----
    cpa16k(A0, g_hEf + eb * 4 * 16384, tid);
    cpa16k(B0, W1, tid);
    CP_COMMIT();                                               // G1
    cpa16k(A1, g_hEf + (eb * 4 + 1) * 16384, tid);
    cpa16k(B1, W1 + 16384, tid);
    CP_COMMIT();                                               // G2
    CP_WAIT1(); __syncthreads();                               // G1 done
    chunk_mma(acc, A0, B0, wm, wn, lid);
    __syncthreads();
    cpa16k(A0, g_hEf + (eb * 4 + 2) * 16384, tid);
    cpa16k(B0, W1 + 32768, tid);
    CP_COMMIT();                                               // G3
    CP_WAIT1(); __syncthreads();                               // G2 done
    chunk_mma(acc, A1, B1, wm, wn, lid);
    __syncthreads();
    cpa16k(A1, g_hEf + (eb * 4 + 3) * 16384, tid);
    cpa16k(B1, W1 + 49152, tid);
    CP_COMMIT();                                               // G4
    CP_WAIT1(); __syncthreads();                               // G3 done
    chunk_mma(acc, A0, B0, wm, wn, lid);
    __syncthreads();
    cpa16k(B0, W2, tid);
    CP_COMMIT();                                               // G5
    CP_WAIT1(); __syncthreads();                               // G4 done
    chunk_mma(acc, A1, B1, wm, wn, lid);
    __syncthreads();
    cpa16k(B1, W2 + 16384, tid);
    CP_COMMIT();                                               // G6
    // t1 = gelu(D + (P[ce] | bv1)) -> T
    epi_store(acc, sm + OFF_T, mode ? g_P : b1, ce, mode != 0, wm, wn, lid);
    __syncthreads();

    // ---- L2: t1 @ W2^T ----
    ZERO_ACC(acc);
    CP_WAIT1(); __syncthreads();                               // G5 done
    chunk_mma(acc, T, B0, wm, wn, lid);
    CP_WAIT0(); __syncthreads();                               // G6 done
    chunk_mma(acc, T + 16384, B1, wm, wn, lid);
    __syncthreads();

    // ---- L3 ----
    if (mode) {
        // Wb3 (4KB) -> B0, overlapped with t2 epilogue
        cp16(B0 + tid * 16, (const char*)g_wb3f + tid * 16);
        CP_COMMIT();
        epi_store(acc, sm + OFF_T, b2, ce, false, wm, wn, lid);   // t2 -> T
        __syncthreads();
        CP_WAIT0(); __syncthreads();
        float accl[4][4];
#pragma unroll
        for (int i = 0; i < 4; ++i)
#pragma unroll
            for (int k = 0; k < 4; ++k) accl[i][k] = 0.f;
        if (wn == 0) {
            chunk_mma_log(accl, T, B0, wm, lid);
            chunk_mma_log(accl, T + 16384, B0 + 2048, wm, lid);
        }
        if (wn == 0 && (lid & 3) < 2) {
            const float rs = 0.17677669529663687f;  // 1/sqrt(32)
            int n = (lid & 3) * 2;
            float bn0 = b3[n], bn1 = b3[n + 1];
#pragma unroll
            for (int ms = 0; ms < 4; ++ms) {
                int r0 = wm * 64 + ms * 16 + (lid >> 2), r1 = r0 + 8;
                float w0 = __expf((accl[ms][0] + bn0) * rs);
                float w1 = __expf((accl[ms][1] + bn1) * rs);
                float w2 = __expf((accl[ms][2] + bn0) * rs);
                float w3 = __expf((accl[ms][3] + bn1) * rs);
                g_ew[(e0 + r0) * 4 + n] = w0;
                g_ew[(e0 + r0) * 4 + n + 1] = w1;
                g_ew[(e0 + r1) * 4 + n] = w2;
                g_ew[(e0 + r1) * 4 + n + 1] = w3;
                if (e0 + r0 < N_EDGES)
                    red2(&g_den[(size_t)ce[r0] * 4 + n], w0, w1);
                if (e0 + r1 < N_EDGES)
                    red2(&g_den[(size_t)ce[r1] * 4 + n], w2, w3);
            }
        }
    } else {
        // Wv3 loads overlapped with t2 epilogue + ew fetch
        cpa16k(B0, (const char*)g_wv3f, tid);
        CP_COMMIT();                                            // G7
        cpa16k(B1, (const char*)g_wv3f + 16384, tid);
        CP_COMMIT();                                            // G8
        epi_store(acc, sm + OFF_T, b2, ce, false, wm, wn, lid);    // t2 -> T
        if (tid < 128)
            *(float4*)(sew + tid * 4) = *(const float4*)(g_ew + (e0 + tid) * 4);
        __syncthreads();
        ZERO_ACC(acc);
        CP_WAIT1(); __syncthreads();                            // G7 done
        chunk_mma(acc, T, B0, wm, wn, lid);
        CP_WAIT0(); __syncthreads();                            // G8 done
        chunk_mma(acc, T + 16384, B1, wm, wn, lid);

        // scatter: lane-pair shuffle -> 16B red.v4 (even lanes: r0, odd: r1)
        int odd = lid & 1;
#pragma unroll
        for (int ms = 0; ms < 4; ++ms) {
            int r0 = wm * 64 + ms * 16 + (lid >> 2), r1 = r0 + 8;
            float ew0 = sew[r0 * 4 + wn], ew1 = sew[r1 * 4 + wn];
            bool v0 = (e0 + r0) < N_EDGES, v1 = (e0 + r1) < N_EDGES;
            float* d0 = g_num + (size_t)ce[r0] * 128;
            float* d1 = g_num + (size_t)ce[r1] * 128;
#pragma unroll
            for (int ns = 0; ns < 4; ++ns) {
                int n = wn * 32 + ns * 8 + (lid & 3) * 2;
                float b0 = b3[n], b1v = b3[n + 1];
                float x0 = acc[ms][ns][0] + b0, x1 = acc[ms][ns][1] + b1v;
                float x2 = acc[ms][ns][2] + b0, x3 = acc[ms][ns][3] + b1v;
                float s0 = __shfl_xor_sync(0xffffffffu, odd ? x0 : x2, 1);
                float s1 = __shfl_xor_sync(0xffffffffu, odd ? x1 : x3, 1);
                if (!odd) {
                    if (v0) red4(d0 + n, ew0 * x0, ew0 * x1, ew0 * s0, ew0 * s1);
                } else {
                    if (v1) red4(d1 + n - 2, ew1 * s0, ew1 * s1, ew1 * x2, ew1 * x3);
                }
            }
        }
    }
}

// ---------------- output projection via HMMA ------------------------------------
// out = (num/den) @ Wo^T ; M=128 nodes per CTA, same structure as k_pre2
extern "C" __global__ void __launch_bounds__(256)
k_out2(float* __restrict__ out) {
    extern __shared__ char sm[];
    uint32_t smb = smem_to_u32(sm);
    int tid = threadIdx.x, wid = tid >> 5, lid = tid & 31;
    int wm = wid & 1, wn = wid >> 1;
    int n0 = blockIdx.x * 128;

    cpa16k(smb + 32768, (const char*)g_wof, tid);
    cpa16k(smb + 49152, (const char*)g_wof + 16384, tid);
    CP_COMMIT();

    // build normalized agg tile in fp16 (2 chunks)
    for (int u = tid; u < 4096; u += 256) {
        int m = u >> 5, q = u & 31;
        int c = q >> 4, q15 = q & 15;
        float4 v = make_float4(0.f, 0.f, 0.f, 0.f);
        if (n0 + m < N_NODES) {
            v = *(const float4*)(g_num + (size_t)(n0 + m) * 128 + q * 4);
            float d = g_den[(size_t)(n0 + m) * 4 + (q >> 3)];
            float r = (d > 0.f) ? (1.0f / d) : 0.f;
            v.x *= r; v.y *= r; v.z *= r; v.w *= r;
        }
        *(uint2*)(sm + c * 16384 + sw128((unsigned)(m * 128 + q15 * 8))) =
            make_uint2(pack_h2(v.x, v.y), pack_h2(v.z, v.w));
    }
    CP_WAIT0();
    __syncthreads();

    float acc[4][4][4];
    ZERO_ACC(acc);
    chunk_mma(acc, smb,         smb + 32768, wm, wn, lid);
    chunk_mma(acc, smb + 16384, smb + 49152, wm, wn, lid);

#pragma unroll
    for (int ms = 0; ms < 4; ++ms) {
        int r0 = wm * 64 + ms * 16 + (lid >> 2), r1 = r0 + 8;
#pragma unroll
        for (int ns = 0; ns < 4; ++ns) {
            int n = wn * 32 + ns * 8 + (lid & 3) * 2;
            if (n0 + r0 < N_NODES) {
                out[(size_t)(n0 + r0) * 128 + n]     = acc[ms][ns][0];
                out[(size_t)(n0 + r0) * 128 + n + 1] = acc[ms][ns][1];
            }
            if (n0 + r1 < N_NODES) {
                out[(size_t)(n0 + r1) * 128 + n]     = acc[ms][ns][2];
                out[(size_t)(n0 + r1) * 128 + n + 1] = acc[ms][ns][3];
            }
        }
    }
}

// ---------------- launch --------------------------------------------------------
extern "C" void kernel_launch(void* const* d_in, const int* in_sizes, int n_in,
                              void* d_out, int out_size) {
    const float* hV  = (const float*)d_in[0];
    const float* hE  = (const float*)d_in[1];
    const float* Wv1 = (const float*)d_in[2];
    const float* bv1 = (const float*)d_in[3];
    const float* Wv2 = (const float*)d_in[4];
    const float* bv2 = (const float*)d_in[5];
    const float* Wv3 = (const float*)d_in[6];
    const float* bv3 = (const float*)d_in[7];
    const float* Wb1 = (const float*)d_in[8];
    const float* bb1 = (const float*)d_in[9];
    const float* Wb2 = (const float*)d_in[10];
    const float* bb2 = (const float*)d_in[11];
    const float* Wb3 = (const float*)d_in[12];
    const float* bb3 = (const float*)d_in[13];
    const float* Wo  = (const float*)d_in[14];
    const int*   cid = (const int*)d_in[15];
    float* out = (float*)d_out;

    void *numPtr, *denPtr;
    cudaGetSymbolAddress(&numPtr, g_num);
    cudaGetSymbolAddress(&denPtr, g_den);

    cudaFuncSetAttribute(k_edge, cudaFuncAttributeMaxDynamicSharedMemorySize, SMEM_E);
    cudaFuncSetAttribute(k_pre2, cudaFuncAttributeMaxDynamicSharedMemorySize, SMEM_P);
    cudaFuncSetAttribute(k_out2, cudaFuncAttributeMaxDynamicSharedMemorySize, SMEM_P);

    cudaMemsetAsync(numPtr, 0, (size_t)N_NODES * HDIM * sizeof(float));
    cudaMemsetAsync(denPtr, 0, (size_t)N_NODES * NHEADS * sizeof(float));
    k_wconv_all<<<584, 256>>>(Wv1, Wv2, Wv3, Wb1, Wb2, Wb3, Wo);
    k_econv<<<(EB * 128 * 32 + 1023) / 1024, 256>>>(hE);
    k_pre2<<<(N_NODES + 127) / 128, 256, SMEM_P>>>(hV, bb1);
    k_edge<<<EB, 256, SMEM_E>>>(1, cid, bb1, bb2, bb3);   // bias MLP -> ew, den
    k_edge<<<EB, 256, SMEM_E>>>(0, cid, bv1, bv2, bv3);   // value MLP -> num
    k_out2<<<(N_NODES + 127) / 128, 256, SMEM_P>>>(out);
}